// round 1
// baseline (speedup 1.0000x reference)
#include <cuda_runtime.h>

// Problem constants
#define KW 7
#define PADV 3
#define CC 256
#define BB 4
#define HH 32
#define WW 32
#define HWN 1024          // 32*32
#define PH 38
#define PW 38
#define PHW 1444          // 38*38

// Scratch (device globals -- no allocation allowed)
__device__ float g_q[BB * CC * HWN];   // [b][c][h*32+w]
__device__ float g_k[BB * CC * PHW];   // [b][c][(h+3)*38+(w+3)] padded plane
__device__ float g_v[BB * CC * PHW];

// ---------------------------------------------------------------------------
// Zero the padded k/v scratch (borders must be zero; interior overwritten by GEMM)
// ---------------------------------------------------------------------------
__global__ void zero_kv_kernel() {
    int i = blockIdx.x * blockDim.x + threadIdx.x;
    const int n4 = (BB * CC * PHW) / 4;   // 369664, divisible
    if (i < n4) {
        float4 z = make_float4(0.f, 0.f, 0.f, 0.f);
        ((float4*)g_k)[i] = z;
        ((float4*)g_v)[i] = z;
    }
}

// ---------------------------------------------------------------------------
// Fused QKV 1x1-conv GEMM:  out[o, n] = sum_c W[o,c] * x[b, c, n]
// grid: x = 32 tiles (2 m-tiles x 16 n-tiles), y = batch, z = {q,k,v}
// BM=128, BN=64, BK=16, 256 threads, 8x4 accum per thread.
// ---------------------------------------------------------------------------
#define BM 128
#define BN 64
#define BKK 16

__global__ __launch_bounds__(256) void qkv_gemm_kernel(
    const float* __restrict__ x,
    const float* __restrict__ wq,
    const float* __restrict__ wk,
    const float* __restrict__ wv)
{
    __shared__ float Ws[BKK][BM];   // transposed: [k][m]
    __shared__ float Xs[BKK][BN];   // [k][n]

    const int mat = blockIdx.z;
    const int b   = blockIdx.y;
    const int mt  = blockIdx.x >> 4;        // 0..1
    const int nt  = blockIdx.x & 15;        // 0..15
    const int m0  = mt * BM;
    const int n0  = nt * BN;

    const float* Wp = (mat == 0) ? wq : ((mat == 1) ? wk : wv);
    const float* Xp = x + (size_t)b * CC * HWN;

    const int tid = threadIdx.x;
    const int ty  = tid >> 4;   // 0..15 -> m group of 8
    const int tx  = tid & 15;   // 0..15 -> n group of 4

    float acc[8][4];
    #pragma unroll
    for (int i = 0; i < 8; i++)
        #pragma unroll
        for (int j = 0; j < 4; j++) acc[i][j] = 0.f;

    for (int k0 = 0; k0 < CC; k0 += BKK) {
        // W tile: 128 rows x 16 cols = 512 float4, 2 per thread
        #pragma unroll
        for (int r = 0; r < 2; r++) {
            int fi  = tid + r * 256;       // 0..511
            int row = fi >> 2;             // 0..127
            int c4  = (fi & 3) * 4;        // 0,4,8,12
            float4 wv4 = *(const float4*)(Wp + (size_t)(m0 + row) * CC + k0 + c4);
            Ws[c4 + 0][row] = wv4.x;
            Ws[c4 + 1][row] = wv4.y;
            Ws[c4 + 2][row] = wv4.z;
            Ws[c4 + 3][row] = wv4.w;
        }
        // X tile: 16 rows x 64 cols = 256 float4, 1 per thread
        {
            int row = tid >> 4;            // 0..15
            int c4  = (tid & 15) * 4;      // 0..60
            *(float4*)&Xs[row][c4] =
                *(const float4*)(Xp + (size_t)(k0 + row) * HWN + n0 + c4);
        }
        __syncthreads();

        #pragma unroll
        for (int kk = 0; kk < BKK; kk++) {
            float a[8], bf[4];
            float4 a0 = *(float4*)&Ws[kk][ty * 8];
            float4 a1 = *(float4*)&Ws[kk][ty * 8 + 4];
            a[0] = a0.x; a[1] = a0.y; a[2] = a0.z; a[3] = a0.w;
            a[4] = a1.x; a[5] = a1.y; a[6] = a1.z; a[7] = a1.w;
            float4 b0 = *(float4*)&Xs[kk][tx * 4];
            bf[0] = b0.x; bf[1] = b0.y; bf[2] = b0.z; bf[3] = b0.w;
            #pragma unroll
            for (int i = 0; i < 8; i++)
                #pragma unroll
                for (int j = 0; j < 4; j++)
                    acc[i][j] = fmaf(a[i], bf[j], acc[i][j]);
        }
        __syncthreads();
    }

    // Store
    if (mat == 0) {
        #pragma unroll
        for (int i = 0; i < 8; i++) {
            int o = m0 + ty * 8 + i;
            float4 r = make_float4(acc[i][0], acc[i][1], acc[i][2], acc[i][3]);
            *(float4*)(g_q + ((size_t)(b * CC + o)) * HWN + n0 + tx * 4) = r;
        }
    } else {
        float* outp = (mat == 1) ? g_k : g_v;
        int n = n0 + tx * 4;
        int h = n >> 5;
        int w = n & 31;                    // w..w+3 stay in-row (4 | 32)
        int pidx = (h + PADV) * PW + (w + PADV);
        #pragma unroll
        for (int i = 0; i < 8; i++) {
            int o = m0 + ty * 8 + i;
            float* p = outp + ((size_t)(b * CC + o)) * PHW + pidx;
            p[0] = acc[i][0];
            p[1] = acc[i][1];
            p[2] = acc[i][2];
            p[3] = acc[i][3];
        }
    }
}

// ---------------------------------------------------------------------------
// Windowed softmax attention. One block per (c, b). k/v planes in smem.
// ---------------------------------------------------------------------------
__global__ __launch_bounds__(256) void attn_kernel(
    const float* __restrict__ rel_h,
    const float* __restrict__ rel_w,
    float* __restrict__ out)
{
    __shared__ float ks[PHW];
    __shared__ float vs[PHW];
    __shared__ float bias_s[KW * KW];

    const int c = blockIdx.x;
    const int b = blockIdx.y;
    const int tid = threadIdx.x;

    const float* kg = g_k + ((size_t)(b * CC + c)) * PHW;
    const float* vg = g_v + ((size_t)(b * CC + c)) * PHW;
    for (int i = tid; i < PHW; i += 256) {
        ks[i] = kg[i];
        vs[i] = vg[i];
    }
    if (tid < KW * KW) {
        int u = tid / KW, v = tid % KW;
        bias_s[tid] = (c < CC / 2) ? rel_h[c * KW + u]
                                   : rel_w[(c - CC / 2) * KW + v];
    }
    __syncthreads();

    const float* qg = g_q + ((size_t)(b * CC + c)) * HWN;
    float*       og = out + ((size_t)(b * CC + c)) * HWN;

    for (int p = tid; p < HWN; p += 256) {
        int h = p >> 5;
        int w = p & 31;
        float q = qg[p];

        float s[KW * KW];
        float m = -1e30f;
        #pragma unroll
        for (int u = 0; u < KW; u++) {
            #pragma unroll
            for (int v = 0; v < KW; v++) {
                int j = u * KW + v;
                float kval = ks[(h + u) * PW + (w + v)] + bias_s[j];
                s[j] = q * kval;
                m = fmaxf(m, s[j]);
            }
        }
        float sum = 0.f, accv = 0.f;
        #pragma unroll
        for (int u = 0; u < KW; u++) {
            #pragma unroll
            for (int v = 0; v < KW; v++) {
                int j = u * KW + v;
                float e = __expf(s[j] - m);
                sum  += e;
                accv  = fmaf(e, vs[(h + u) * PW + (w + v)], accv);
            }
        }
        og[p] = accv * (1.0f / sum);
    }
}

// ---------------------------------------------------------------------------
extern "C" void kernel_launch(void* const* d_in, const int* in_sizes, int n_in,
                              void* d_out, int out_size)
{
    const float* x     = (const float*)d_in[0];
    const float* wq    = (const float*)d_in[1];
    const float* wk    = (const float*)d_in[2];
    const float* wv    = (const float*)d_in[3];
    const float* rel_h = (const float*)d_in[4];
    const float* rel_w = (const float*)d_in[5];
    float* out = (float*)d_out;

    // 1) zero padded k/v scratch (borders must be zero every call)
    zero_kv_kernel<<<(BB * CC * PHW / 4 + 255) / 256, 256>>>();

    // 2) q/k/v 1x1-conv GEMMs (interior only for k/v)
    dim3 gg(32, BB, 3);
    qkv_gemm_kernel<<<gg, 256>>>(x, wq, wk, wv);

    // 3) windowed softmax attention
    dim3 ga(CC, BB);
    attn_kernel<<<ga, 256>>>(rel_h, rel_w, out);
}

// round 3
// speedup vs baseline: 1.8523x; 1.8523x over previous
#include <cuda_runtime.h>
#include <cuda_bf16.h>
#include <cstdint>

// Problem constants
#define KW 7
#define CC 256
#define BB 4
#define HWN 1024          // 32*32
#define PW 38
#define PHW 1444          // 38*38

// Scratch (device globals, unpadded)
__device__ float g_q[BB * CC * HWN];
__device__ float g_k[BB * CC * HWN];
__device__ float g_v[BB * CC * HWN];

// ---------------------------------------------------------------------------
// helpers
// ---------------------------------------------------------------------------
__device__ __forceinline__ uint32_t smem_u32(const void* p) {
    uint32_t a;
    asm("{ .reg .u64 t; cvta.to.shared.u64 t, %1; cvt.u32.u64 %0, t; }" : "=r"(a) : "l"(p));
    return a;
}
__device__ __forceinline__ void ldsm_x4(uint32_t r[4], uint32_t addr) {
    asm volatile("ldmatrix.sync.aligned.m8n8.x4.shared.b16 {%0,%1,%2,%3}, [%4];"
                 : "=r"(r[0]), "=r"(r[1]), "=r"(r[2]), "=r"(r[3]) : "r"(addr));
}
__device__ __forceinline__ void ldsm_x4_t(uint32_t r[4], uint32_t addr) {
    asm volatile("ldmatrix.sync.aligned.m8n8.x4.trans.shared.b16 {%0,%1,%2,%3}, [%4];"
                 : "=r"(r[0]), "=r"(r[1]), "=r"(r[2]), "=r"(r[3]) : "r"(addr));
}
__device__ __forceinline__ void mma_bf16(float c[4], const uint32_t a[4],
                                         uint32_t b0, uint32_t b1) {
    asm volatile(
        "mma.sync.aligned.m16n8k16.row.col.f32.bf16.bf16.f32 "
        "{%0,%1,%2,%3}, {%4,%5,%6,%7}, {%8,%9}, {%0,%1,%2,%3};"
        : "+f"(c[0]), "+f"(c[1]), "+f"(c[2]), "+f"(c[3])
        : "r"(a[0]), "r"(a[1]), "r"(a[2]), "r"(a[3]), "r"(b0), "r"(b1));
}
__device__ __forceinline__ void split_bf(float a, __nv_bfloat16& h, __nv_bfloat16& l) {
    h = __float2bfloat16(a);
    l = __float2bfloat16(a - __bfloat162float(h));
}
__device__ __forceinline__ uint32_t pack2(__nv_bfloat16 a, __nv_bfloat16 b) {
    __nv_bfloat162 t; t.x = a; t.y = b;
    return *(uint32_t*)&t;
}

// ---------------------------------------------------------------------------
// bf16 split-precision QKV GEMM via mma.sync
// out[o,n] = sum_c W[o,c] * x[b,c,n];   128x128 CTA tile, BK=32, 8 warps.
// grid: x = 16 (2 m-tiles x 8 n-tiles), y = batch(4), z = mat(3)
// ---------------------------------------------------------------------------
#define SKA 48    // A smem stride (halves): 96B rows, 16B-aligned
#define SKB 136   // B smem stride (halves): 272B rows, 16B-aligned

__global__ __launch_bounds__(256) void qkv_mma_kernel(
    const float* __restrict__ x,
    const float* __restrict__ wq,
    const float* __restrict__ wk,
    const float* __restrict__ wv)
{
    __shared__ __nv_bfloat16 Ah[128 * SKA];
    __shared__ __nv_bfloat16 Al[128 * SKA];
    __shared__ __nv_bfloat16 Bh[32 * SKB];
    __shared__ __nv_bfloat16 Bl[32 * SKB];

    const int tid  = threadIdx.x;
    const int wid  = tid >> 5;
    const int lane = tid & 31;
    const int wm   = wid >> 1;          // 0..3
    const int wn   = wid & 1;           // 0..1
    const int mat  = blockIdx.z;
    const int b    = blockIdx.y;
    const int m0   = (blockIdx.x >> 3) * 128;
    const int n0   = (blockIdx.x & 7) * 128;

    const float* W = (mat == 0) ? wq : (mat == 1) ? wk : wv;
    const float* X = x + (size_t)b * CC * HWN;
    float* outp = (mat == 0) ? g_q : (mat == 1) ? g_k : g_v;

    float acc[2][8][4];
    #pragma unroll
    for (int i = 0; i < 2; i++)
        #pragma unroll
        for (int j = 0; j < 8; j++)
            #pragma unroll
            for (int r = 0; r < 4; r++) acc[i][j][r] = 0.f;

    const uint32_t ah_base = smem_u32(Ah);
    const uint32_t al_base = smem_u32(Al);
    const uint32_t bh_base = smem_u32(Bh);
    const uint32_t bl_base = smem_u32(Bl);

    for (int ch = 0; ch < 8; ch++) {
        const int k0 = ch * 32;
        // ---- A tile: W[m0..+127][k0..+31]  (1024 float4, 4 per thread)
        #pragma unroll
        for (int t = 0; t < 4; t++) {
            int idx = tid + t * 256;
            int row = idx >> 3;
            int c4  = (idx & 7) << 2;
            float4 w4 = *(const float4*)(W + (size_t)(m0 + row) * CC + k0 + c4);
            __nv_bfloat16 hx, lx, hy, ly, hz, lz, hw, lw;
            split_bf(w4.x, hx, lx); split_bf(w4.y, hy, ly);
            split_bf(w4.z, hz, lz); split_bf(w4.w, hw, lw);
            int off = row * SKA + c4;
            *(uint2*)&Ah[off] = make_uint2(pack2(hx, hy), pack2(hz, hw));
            *(uint2*)&Al[off] = make_uint2(pack2(lx, ly), pack2(lz, lw));
        }
        // ---- B tile: X[k0..+31][n0..+127] stored [k][n] (coalesced)
        #pragma unroll
        for (int t = 0; t < 4; t++) {
            int idx = tid + t * 256;
            int kk  = idx >> 5;
            int n4  = (idx & 31) << 2;
            float4 xv = *(const float4*)(X + (size_t)(k0 + kk) * HWN + n0 + n4);
            __nv_bfloat16 hx, lx, hy, ly, hz, lz, hw, lw;
            split_bf(xv.x, hx, lx); split_bf(xv.y, hy, ly);
            split_bf(xv.z, hz, lz); split_bf(xv.w, hw, lw);
            int off = kk * SKB + n4;
            *(uint2*)&Bh[off] = make_uint2(pack2(hx, hy), pack2(hz, hw));
            *(uint2*)&Bl[off] = make_uint2(pack2(lx, ly), pack2(lz, lw));
        }
        __syncthreads();

        #pragma unroll
        for (int ks = 0; ks < 2; ks++) {
            const int kk = ks * 16;
            // A fragments (2 m16 tiles), hi & lo
            uint32_t afh[2][4], afl[2][4];
            #pragma unroll
            for (int mt = 0; mt < 2; mt++) {
                uint32_t aoff = (uint32_t)((wm * 32 + mt * 16 + (lane & 15)) * SKA
                                           + kk + ((lane >> 4) << 3)) * 2u;
                ldsm_x4(afh[mt], ah_base + aoff);
                ldsm_x4(afl[mt], al_base + aoff);
            }
            // B fragments (8 n8 tiles = 4 ldmatrix.x4.trans), hi & lo
            uint32_t bfh[8][2], bfl[8][2];
            #pragma unroll
            for (int p = 0; p < 4; p++) {
                uint32_t boff = (uint32_t)((kk + (lane & 15)) * SKB
                                           + wn * 64 + p * 16 + ((lane >> 4) << 3)) * 2u;
                uint32_t r[4];
                ldsm_x4_t(r, bh_base + boff);
                bfh[p * 2][0] = r[0]; bfh[p * 2][1] = r[1];
                bfh[p * 2 + 1][0] = r[2]; bfh[p * 2 + 1][1] = r[3];
                ldsm_x4_t(r, bl_base + boff);
                bfl[p * 2][0] = r[0]; bfl[p * 2][1] = r[1];
                bfl[p * 2 + 1][0] = r[2]; bfl[p * 2 + 1][1] = r[3];
            }
            #pragma unroll
            for (int mt = 0; mt < 2; mt++)
                #pragma unroll
                for (int nt = 0; nt < 8; nt++) {
                    mma_bf16(acc[mt][nt], afh[mt], bfh[nt][0], bfh[nt][1]);
                    mma_bf16(acc[mt][nt], afh[mt], bfl[nt][0], bfl[nt][1]);
                    mma_bf16(acc[mt][nt], afl[mt], bfh[nt][0], bfh[nt][1]);
                }
        }
        __syncthreads();
    }

    // ---- epilogue
    #pragma unroll
    for (int mt = 0; mt < 2; mt++) {
        int o = m0 + wm * 32 + mt * 16 + (lane >> 2);
        #pragma unroll
        for (int nt = 0; nt < 8; nt++) {
            int n = n0 + wn * 64 + nt * 8 + ((lane & 3) << 1);
            float* og = outp + ((size_t)(b * CC + o)) * HWN + n;
            *(float2*)og = make_float2(acc[mt][nt][0], acc[mt][nt][1]);
            *(float2*)(og + 8 * HWN) = make_float2(acc[mt][nt][2], acc[mt][nt][3]);
        }
    }
}

// ---------------------------------------------------------------------------
// Windowed softmax attention. One block per (c, b). Unpadded k/v -> padded smem.
// ---------------------------------------------------------------------------
__device__ __forceinline__ float ex2f(float x) {
    float y;
    asm("ex2.approx.ftz.f32 %0, %1;" : "=f"(y) : "f"(x));
    return y;
}

__global__ __launch_bounds__(256) void attn_kernel(
    const float* __restrict__ rel_h,
    const float* __restrict__ rel_w,
    float* __restrict__ out)
{
    __shared__ float ks[PHW];
    __shared__ float vs[PHW];
    __shared__ float brow_s[8];

    const int c = blockIdx.x;
    const int b = blockIdx.y;
    const int tid = threadIdx.x;
    const bool hsel = (c < CC / 2);

    for (int i = tid; i < PHW; i += 256) { ks[i] = 0.f; vs[i] = 0.f; }
    if (tid < KW)
        brow_s[tid] = hsel ? rel_h[c * KW + tid] : rel_w[(c - CC / 2) * KW + tid];
    __syncthreads();

    const float* kg = g_k + ((size_t)(b * CC + c)) * HWN;
    const float* vg = g_v + ((size_t)(b * CC + c)) * HWN;
    for (int p = tid; p < HWN; p += 256) {
        int h = p >> 5, w = p & 31;
        int pi = (h + 3) * PW + (w + 3);
        ks[pi] = kg[p];
        vs[pi] = vg[p];
    }
    __syncthreads();

    const float* qg = g_q + ((size_t)(b * CC + c)) * HWN;
    float*       og = out + ((size_t)(b * CC + c)) * HWN;

    const int p0 = tid * 4;
    const int h  = p0 >> 5;
    const int w0 = p0 & 31;
    const float LOG2E = 1.4426950408889634f;

    float4 qv = *(const float4*)(qg + p0);
    float q2[4] = { qv.x * LOG2E, qv.y * LOG2E, qv.z * LOG2E, qv.w * LOG2E };
    float qb[4][KW];
    #pragma unroll
    for (int j = 0; j < 4; j++)
        #pragma unroll
        for (int i = 0; i < KW; i++)
            qb[j][i] = q2[j] * brow_s[i];

    float acc[4] = {0.f, 0.f, 0.f, 0.f};
    float sum[4] = {0.f, 0.f, 0.f, 0.f};

    #pragma unroll
    for (int u = 0; u < KW; u++) {
        const int rbase = (h + u) * PW + w0;
        float kr[10], vr[10];
        #pragma unroll
        for (int i = 0; i < 10; i++) { kr[i] = ks[rbase + i]; vr[i] = vs[rbase + i]; }
        #pragma unroll
        for (int v = 0; v < KW; v++) {
            #pragma unroll
            for (int j = 0; j < 4; j++) {
                float bb = hsel ? qb[j][u] : qb[j][v];
                float t  = fmaf(q2[j], kr[v + j], bb);
                float e  = ex2f(t);
                sum[j] += e;
                acc[j]  = fmaf(e, vr[v + j], acc[j]);
            }
        }
    }

    float4 r;
    r.x = __fdividef(acc[0], sum[0]);
    r.y = __fdividef(acc[1], sum[1]);
    r.z = __fdividef(acc[2], sum[2]);
    r.w = __fdividef(acc[3], sum[3]);
    *(float4*)(og + p0) = r;
}

// ---------------------------------------------------------------------------
extern "C" void kernel_launch(void* const* d_in, const int* in_sizes, int n_in,
                              void* d_out, int out_size)
{
    const float* x     = (const float*)d_in[0];
    const float* wq    = (const float*)d_in[1];
    const float* wk    = (const float*)d_in[2];
    const float* wv    = (const float*)d_in[3];
    const float* rel_h = (const float*)d_in[4];
    const float* rel_w = (const float*)d_in[5];
    float* out = (float*)d_out;

    dim3 gg(16, BB, 3);
    qkv_mma_kernel<<<gg, 256>>>(x, wq, wk, wv);

    dim3 ga(CC, BB);
    attn_kernel<<<ga, 256>>>(rel_h, rel_w, out);
}

// round 4
// speedup vs baseline: 1.9328x; 1.0434x over previous
#include <cuda_runtime.h>
#include <cuda_bf16.h>
#include <cstdint>

// Problem constants
#define KW 7
#define CC 256
#define BB 4
#define HWN 1024          // 32*32
#define PW 38
#define PHW 1444          // 38*38

// Scratch (device globals, unpadded)
__device__ float g_q[BB * CC * HWN];
__device__ float g_k[BB * CC * HWN];
__device__ float g_v[BB * CC * HWN];

// ---------------------------------------------------------------------------
// helpers
// ---------------------------------------------------------------------------
__device__ __forceinline__ uint32_t smem_u32(const void* p) {
    uint32_t a;
    asm("{ .reg .u64 t; cvta.to.shared.u64 t, %1; cvt.u32.u64 %0, t; }" : "=r"(a) : "l"(p));
    return a;
}
__device__ __forceinline__ void ldsm_x4(uint32_t r[4], uint32_t addr) {
    asm volatile("ldmatrix.sync.aligned.m8n8.x4.shared.b16 {%0,%1,%2,%3}, [%4];"
                 : "=r"(r[0]), "=r"(r[1]), "=r"(r[2]), "=r"(r[3]) : "r"(addr));
}
__device__ __forceinline__ void ldsm_x4_t(uint32_t r[4], uint32_t addr) {
    asm volatile("ldmatrix.sync.aligned.m8n8.x4.trans.shared.b16 {%0,%1,%2,%3}, [%4];"
                 : "=r"(r[0]), "=r"(r[1]), "=r"(r[2]), "=r"(r[3]) : "r"(addr));
}
__device__ __forceinline__ void mma_bf16(float c[4], const uint32_t a[4],
                                         uint32_t b0, uint32_t b1) {
    asm volatile(
        "mma.sync.aligned.m16n8k16.row.col.f32.bf16.bf16.f32 "
        "{%0,%1,%2,%3}, {%4,%5,%6,%7}, {%8,%9}, {%0,%1,%2,%3};"
        : "+f"(c[0]), "+f"(c[1]), "+f"(c[2]), "+f"(c[3])
        : "r"(a[0]), "r"(a[1]), "r"(a[2]), "r"(a[3]), "r"(b0), "r"(b1));
}
__device__ __forceinline__ void split_bf(float a, __nv_bfloat16& h, __nv_bfloat16& l) {
    h = __float2bfloat16(a);
    l = __float2bfloat16(a - __bfloat162float(h));
}
__device__ __forceinline__ uint32_t pack2(__nv_bfloat16 a, __nv_bfloat16 b) {
    __nv_bfloat162 t; t.x = a; t.y = b;
    return *(uint32_t*)&t;
}

// ---------------------------------------------------------------------------
// bf16 split-precision QKV GEMM via mma.sync, double-buffered smem pipeline.
// out[o,n] = sum_c W[o,c] * x[b,c,n];   128x128 CTA tile, BK=32, 8 warps.
// grid: x = 16 (2 m-tiles x 8 n-tiles), y = batch(4), z = mat(3)
// ---------------------------------------------------------------------------
#define SKA 48      // A smem stride (halves)
#define SKB 136     // B smem stride (halves)
#define OFF_AL 12288
#define OFF_BH 24576
#define OFF_BL 33280
#define STG_BYTES 41984
#define SMEM_TOTAL (2 * STG_BYTES)

__global__ __launch_bounds__(256) void qkv_mma_kernel(
    const float* __restrict__ x,
    const float* __restrict__ wq,
    const float* __restrict__ wk,
    const float* __restrict__ wv)
{
    extern __shared__ char sm[];

    const int tid  = threadIdx.x;
    const int wid  = tid >> 5;
    const int lane = tid & 31;
    const int wm   = wid >> 1;          // 0..3
    const int wn   = wid & 1;           // 0..1
    const int mat  = blockIdx.z;
    const int b    = blockIdx.y;
    const int m0   = (blockIdx.x >> 3) * 128;
    const int n0   = (blockIdx.x & 7) * 128;

    const float* W = (mat == 0) ? wq : (mat == 1) ? wk : wv;
    const float* X = x + (size_t)b * CC * HWN;
    float* outp = (mat == 0) ? g_q : (mat == 1) ? g_k : g_v;

    const uint32_t sm_base = smem_u32(sm);

    // per-thread load coordinates
    const int arow = tid >> 3;                  // 0..31 (A: +t*32 rows)
    const int ac4  = (tid & 7) << 2;            // 0..28
    const int bkk  = tid >> 5;                  // 0..7  (B: +t*8 rows)
    const int bn4  = (tid & 31) << 2;           // 0..124

    const float* Ag = W + (size_t)(m0 + arow) * CC + ac4;
    const float* Bg = X + (size_t)bkk * HWN + n0 + bn4;

    float4 aS[4], bS[4];

    // ---- prologue: load + store chunk 0
    #pragma unroll
    for (int t = 0; t < 4; t++) {
        aS[t] = *(const float4*)(Ag + (size_t)(t * 32) * CC);
        bS[t] = *(const float4*)(Bg + (size_t)(t * 8) * HWN);
    }
    {
        char* st = sm;
        #pragma unroll
        for (int t = 0; t < 4; t++) {
            __nv_bfloat16 hx, lx, hy, ly, hz, lz, hw, lw;
            split_bf(aS[t].x, hx, lx); split_bf(aS[t].y, hy, ly);
            split_bf(aS[t].z, hz, lz); split_bf(aS[t].w, hw, lw);
            int off = ((arow + t * 32) * SKA + ac4) * 2;
            *(uint2*)(st + off) = make_uint2(pack2(hx, hy), pack2(hz, hw));
            *(uint2*)(st + OFF_AL + off) = make_uint2(pack2(lx, ly), pack2(lz, lw));
            split_bf(bS[t].x, hx, lx); split_bf(bS[t].y, hy, ly);
            split_bf(bS[t].z, hz, lz); split_bf(bS[t].w, hw, lw);
            int boff = ((bkk + t * 8) * SKB + bn4) * 2;
            *(uint2*)(st + OFF_BH + boff) = make_uint2(pack2(hx, hy), pack2(hz, hw));
            *(uint2*)(st + OFF_BL + boff) = make_uint2(pack2(lx, ly), pack2(lz, lw));
        }
    }
    __syncthreads();

    float acc[2][8][4];
    #pragma unroll
    for (int i = 0; i < 2; i++)
        #pragma unroll
        for (int j = 0; j < 8; j++)
            #pragma unroll
            for (int r = 0; r < 4; r++) acc[i][j][r] = 0.f;

    for (int ch = 0; ch < 8; ch++) {
        // ---- issue next chunk's global loads (overlap with mma)
        if (ch < 7) {
            const int k0 = (ch + 1) * 32;
            #pragma unroll
            for (int t = 0; t < 4; t++) {
                aS[t] = *(const float4*)(Ag + (size_t)(t * 32) * CC + k0);
                bS[t] = *(const float4*)(Bg + (size_t)(k0 + t * 8) * HWN);
            }
        }

        // ---- mma on current stage
        const uint32_t stb = sm_base + (ch & 1) * STG_BYTES;
        #pragma unroll
        for (int ks = 0; ks < 2; ks++) {
            const int kk = ks * 16;
            uint32_t afh[2][4], afl[2][4];
            #pragma unroll
            for (int mt = 0; mt < 2; mt++) {
                uint32_t aoff = (uint32_t)((wm * 32 + mt * 16 + (lane & 15)) * SKA
                                           + kk + ((lane >> 4) << 3)) * 2u;
                ldsm_x4(afh[mt], stb + aoff);
                ldsm_x4(afl[mt], stb + OFF_AL + aoff);
            }
            uint32_t bfh[8][2], bfl[8][2];
            #pragma unroll
            for (int p = 0; p < 4; p++) {
                uint32_t boff = (uint32_t)((kk + (lane & 15)) * SKB
                                           + wn * 64 + p * 16 + ((lane >> 4) << 3)) * 2u;
                uint32_t r[4];
                ldsm_x4_t(r, stb + OFF_BH + boff);
                bfh[p * 2][0] = r[0]; bfh[p * 2][1] = r[1];
                bfh[p * 2 + 1][0] = r[2]; bfh[p * 2 + 1][1] = r[3];
                ldsm_x4_t(r, stb + OFF_BL + boff);
                bfl[p * 2][0] = r[0]; bfl[p * 2][1] = r[1];
                bfl[p * 2 + 1][0] = r[2]; bfl[p * 2 + 1][1] = r[3];
            }
            #pragma unroll
            for (int mt = 0; mt < 2; mt++)
                #pragma unroll
                for (int nt = 0; nt < 8; nt++) {
                    mma_bf16(acc[mt][nt], afh[mt], bfh[nt][0], bfh[nt][1]);
                    mma_bf16(acc[mt][nt], afh[mt], bfl[nt][0], bfl[nt][1]);
                    mma_bf16(acc[mt][nt], afl[mt], bfh[nt][0], bfh[nt][1]);
                }
        }

        // ---- convert + store next stage
        if (ch < 7) {
            char* st = sm + ((ch + 1) & 1) * STG_BYTES;
            #pragma unroll
            for (int t = 0; t < 4; t++) {
                __nv_bfloat16 hx, lx, hy, ly, hz, lz, hw, lw;
                split_bf(aS[t].x, hx, lx); split_bf(aS[t].y, hy, ly);
                split_bf(aS[t].z, hz, lz); split_bf(aS[t].w, hw, lw);
                int off = ((arow + t * 32) * SKA + ac4) * 2;
                *(uint2*)(st + off) = make_uint2(pack2(hx, hy), pack2(hz, hw));
                *(uint2*)(st + OFF_AL + off) = make_uint2(pack2(lx, ly), pack2(lz, lw));
                split_bf(bS[t].x, hx, lx); split_bf(bS[t].y, hy, ly);
                split_bf(bS[t].z, hz, lz); split_bf(bS[t].w, hw, lw);
                int boff = ((bkk + t * 8) * SKB + bn4) * 2;
                *(uint2*)(st + OFF_BH + boff) = make_uint2(pack2(hx, hy), pack2(hz, hw));
                *(uint2*)(st + OFF_BL + boff) = make_uint2(pack2(lx, ly), pack2(lz, lw));
            }
        }
        __syncthreads();
    }

    // ---- epilogue
    #pragma unroll
    for (int mt = 0; mt < 2; mt++) {
        int o = m0 + wm * 32 + mt * 16 + (lane >> 2);
        #pragma unroll
        for (int nt = 0; nt < 8; nt++) {
            int n = n0 + wn * 64 + nt * 8 + ((lane & 3) << 1);
            float* og = outp + ((size_t)(b * CC + o)) * HWN + n;
            *(float2*)og = make_float2(acc[mt][nt][0], acc[mt][nt][1]);
            *(float2*)(og + 8 * HWN) = make_float2(acc[mt][nt][2], acc[mt][nt][3]);
        }
    }
}

// ---------------------------------------------------------------------------
// Windowed softmax attention, hsel-specialized mainloops.
// ---------------------------------------------------------------------------
__device__ __forceinline__ float ex2f(float x) {
    float y;
    asm("ex2.approx.ftz.f32 %0, %1;" : "=f"(y) : "f"(x));
    return y;
}

__global__ __launch_bounds__(256) void attn_kernel(
    const float* __restrict__ rel_h,
    const float* __restrict__ rel_w,
    float* __restrict__ out)
{
    __shared__ float ks[PHW];
    __shared__ float vs[PHW];
    __shared__ float brow_s[8];

    const int c = blockIdx.x;
    const int b = blockIdx.y;
    const int tid = threadIdx.x;
    const bool hsel = (c < CC / 2);

    for (int i = tid; i < PHW; i += 256) { ks[i] = 0.f; vs[i] = 0.f; }
    if (tid < KW)
        brow_s[tid] = hsel ? rel_h[c * KW + tid] : rel_w[(c - CC / 2) * KW + tid];
    __syncthreads();

    const float* kg = g_k + ((size_t)(b * CC + c)) * HWN;
    const float* vg = g_v + ((size_t)(b * CC + c)) * HWN;
    for (int p = tid; p < HWN; p += 256) {
        int h = p >> 5, w = p & 31;
        int pi = (h + 3) * PW + (w + 3);
        ks[pi] = kg[p];
        vs[pi] = vg[p];
    }
    __syncthreads();

    const float* qg = g_q + ((size_t)(b * CC + c)) * HWN;
    float*       og = out + ((size_t)(b * CC + c)) * HWN;

    const int p0 = tid * 4;
    const int h  = p0 >> 5;
    const int w0 = p0 & 31;
    const float LOG2E = 1.4426950408889634f;

    float4 qv = *(const float4*)(qg + p0);
    float q2[4] = { qv.x * LOG2E, qv.y * LOG2E, qv.z * LOG2E, qv.w * LOG2E };
    float qb[4][KW];
    #pragma unroll
    for (int j = 0; j < 4; j++)
        #pragma unroll
        for (int i = 0; i < KW; i++)
            qb[j][i] = q2[j] * brow_s[i];

    float acc[4] = {0.f, 0.f, 0.f, 0.f};
    float sum[4] = {0.f, 0.f, 0.f, 0.f};

    if (hsel) {
        #pragma unroll
        for (int u = 0; u < KW; u++) {
            const int rbase = (h + u) * PW + w0;
            float kr[10], vr[10];
            #pragma unroll
            for (int i = 0; i < 10; i++) { kr[i] = ks[rbase + i]; vr[i] = vs[rbase + i]; }
            #pragma unroll
            for (int v = 0; v < KW; v++) {
                #pragma unroll
                for (int j = 0; j < 4; j++) {
                    float t = fmaf(q2[j], kr[v + j], qb[j][u]);
                    float e = ex2f(t);
                    sum[j] += e;
                    acc[j]  = fmaf(e, vr[v + j], acc[j]);
                }
            }
        }
    } else {
        #pragma unroll
        for (int u = 0; u < KW; u++) {
            const int rbase = (h + u) * PW + w0;
            float kr[10], vr[10];
            #pragma unroll
            for (int i = 0; i < 10; i++) { kr[i] = ks[rbase + i]; vr[i] = vs[rbase + i]; }
            #pragma unroll
            for (int v = 0; v < KW; v++) {
                #pragma unroll
                for (int j = 0; j < 4; j++) {
                    float t = fmaf(q2[j], kr[v + j], qb[j][v]);
                    float e = ex2f(t);
                    sum[j] += e;
                    acc[j]  = fmaf(e, vr[v + j], acc[j]);
                }
            }
        }
    }

    float4 r;
    r.x = __fdividef(acc[0], sum[0]);
    r.y = __fdividef(acc[1], sum[1]);
    r.z = __fdividef(acc[2], sum[2]);
    r.w = __fdividef(acc[3], sum[3]);
    *(float4*)(og + p0) = r;
}

// ---------------------------------------------------------------------------
extern "C" void kernel_launch(void* const* d_in, const int* in_sizes, int n_in,
                              void* d_out, int out_size)
{
    const float* x     = (const float*)d_in[0];
    const float* wq    = (const float*)d_in[1];
    const float* wk    = (const float*)d_in[2];
    const float* wv    = (const float*)d_in[3];
    const float* rel_h = (const float*)d_in[4];
    const float* rel_w = (const float*)d_in[5];
    float* out = (float*)d_out;

    cudaFuncSetAttribute(qkv_mma_kernel, cudaFuncAttributeMaxDynamicSharedMemorySize,
                         SMEM_TOTAL);

    dim3 gg(16, BB, 3);
    qkv_mma_kernel<<<gg, 256, SMEM_TOTAL>>>(x, wq, wk, wv);

    dim3 ga(CC, BB);
    attn_kernel<<<ga, 256>>>(rel_h, rel_w, out);
}

// round 5
// speedup vs baseline: 2.0078x; 1.0388x over previous
#include <cuda_runtime.h>
#include <cuda_bf16.h>
#include <cstdint>

// Problem constants
#define KW 7
#define CC 256
#define BB 4
#define HWN 1024          // 32*32
#define PW 38
#define PHW 1444          // 38*38

// Scratch (device globals)
__device__ float g_q[BB * CC * HWN];
__device__ float g_k[BB * CC * HWN];
__device__ float g_v[BB * CC * HWN];
__device__ __nv_bfloat16 g_Whi[3 * 256 * 256];
__device__ __nv_bfloat16 g_Wlo[3 * 256 * 256];
__device__ __nv_bfloat16 g_Xhi[BB * 256 * 1024];
__device__ __nv_bfloat16 g_Xlo[BB * 256 * 1024];

// ---------------------------------------------------------------------------
// helpers
// ---------------------------------------------------------------------------
__device__ __forceinline__ uint32_t smem_u32(const void* p) {
    uint32_t a;
    asm("{ .reg .u64 t; cvta.to.shared.u64 t, %1; cvt.u32.u64 %0, t; }" : "=r"(a) : "l"(p));
    return a;
}
__device__ __forceinline__ void ldsm_x4(uint32_t r[4], uint32_t addr) {
    asm volatile("ldmatrix.sync.aligned.m8n8.x4.shared.b16 {%0,%1,%2,%3}, [%4];"
                 : "=r"(r[0]), "=r"(r[1]), "=r"(r[2]), "=r"(r[3]) : "r"(addr));
}
__device__ __forceinline__ void ldsm_x4_t(uint32_t r[4], uint32_t addr) {
    asm volatile("ldmatrix.sync.aligned.m8n8.x4.trans.shared.b16 {%0,%1,%2,%3}, [%4];"
                 : "=r"(r[0]), "=r"(r[1]), "=r"(r[2]), "=r"(r[3]) : "r"(addr));
}
__device__ __forceinline__ void mma_bf16(float c[4], const uint32_t a[4],
                                         uint32_t b0, uint32_t b1) {
    asm volatile(
        "mma.sync.aligned.m16n8k16.row.col.f32.bf16.bf16.f32 "
        "{%0,%1,%2,%3}, {%4,%5,%6,%7}, {%8,%9}, {%0,%1,%2,%3};"
        : "+f"(c[0]), "+f"(c[1]), "+f"(c[2]), "+f"(c[3])
        : "r"(a[0]), "r"(a[1]), "r"(a[2]), "r"(a[3]), "r"(b0), "r"(b1));
}
__device__ __forceinline__ void split_bf(float a, __nv_bfloat16& h, __nv_bfloat16& l) {
    h = __float2bfloat16(a);
    l = __float2bfloat16(a - __bfloat162float(h));
}
__device__ __forceinline__ uint32_t pack2(__nv_bfloat16 a, __nv_bfloat16 b) {
    __nv_bfloat162 t; t.x = a; t.y = b;
    return *(uint32_t*)&t;
}
#define CP_ASYNC16(dst, src) \
    asm volatile("cp.async.cg.shared.global [%0], [%1], 16;" :: "r"(dst), "l"(src))
#define CP_COMMIT() asm volatile("cp.async.commit_group;" ::: "memory")
#define CP_WAIT(N)  asm volatile("cp.async.wait_group %0;" :: "n"(N) : "memory")

// ---------------------------------------------------------------------------
// Pre-convert: x -> g_Xhi/g_Xlo, W(q,k,v) -> g_Whi/g_Wlo
// grid 1216 blocks x 256: blocks [0,1024) do X (float4 each), rest do W.
// ---------------------------------------------------------------------------
__global__ __launch_bounds__(256) void convert_kernel(
    const float* __restrict__ x,
    const float* __restrict__ wq,
    const float* __restrict__ wk,
    const float* __restrict__ wv)
{
    const int tid = threadIdx.x;
    __nv_bfloat16 h0, l0, h1, l1, h2, l2, h3, l3;
    if (blockIdx.x < 1024) {
        int i4 = blockIdx.x * 256 + tid;                 // 0..262143
        float4 v = ((const float4*)x)[i4];
        split_bf(v.x, h0, l0); split_bf(v.y, h1, l1);
        split_bf(v.z, h2, l2); split_bf(v.w, h3, l3);
        int base = i4 * 4;
        *(uint2*)&g_Xhi[base] = make_uint2(pack2(h0, h1), pack2(h2, h3));
        *(uint2*)&g_Xlo[base] = make_uint2(pack2(l0, l1), pack2(l2, l3));
    } else {
        int i4 = (blockIdx.x - 1024) * 256 + tid;        // 0..49151
        int mat = i4 >> 14;                              // 16384 float4 per mat
        int off4 = i4 & 16383;
        const float* Wp = (mat == 0) ? wq : (mat == 1) ? wk : wv;
        float4 v = ((const float4*)Wp)[off4];
        split_bf(v.x, h0, l0); split_bf(v.y, h1, l1);
        split_bf(v.z, h2, l2); split_bf(v.w, h3, l3);
        int base = i4 * 4;
        *(uint2*)&g_Whi[base] = make_uint2(pack2(h0, h1), pack2(h2, h3));
        *(uint2*)&g_Wlo[base] = make_uint2(pack2(l0, l1), pack2(l2, l3));
    }
}

// ---------------------------------------------------------------------------
// bf16 split-precision QKV GEMM, cp.async 3-stage pipeline.
// 64x128 tile, BK=32, 8 warps (warptile 32x32).
// grid: x = 96 (12 m-tiles over combined 768 rows x 8 n-tiles), y = batch(4)
// ---------------------------------------------------------------------------
#define SKA 48       // A smem stride (halves)
#define SKB 136      // B smem stride (halves)
#define OFF_AL 6144
#define OFF_BH 12288
#define OFF_BL 20992
#define STG_BYTES 29696
#define SMEM_TOTAL (3 * STG_BYTES)

__global__ __launch_bounds__(256) void qkv_mma_kernel()
{
    extern __shared__ char sm[];
    const uint32_t sm_base = smem_u32(sm);

    const int tid  = threadIdx.x;
    const int wid  = tid >> 5;
    const int lane = tid & 31;
    const int wm   = wid >> 2;          // 0..1 (32 rows)
    const int wn   = wid & 3;           // 0..3 (32 cols)
    const int b    = blockIdx.y;
    const int m0g  = (blockIdx.x >> 3) * 64;   // 0..704 combined row
    const int n0   = (blockIdx.x & 7) * 128;

    // per-thread cp.async coordinates
    const int ar  = tid >> 2;            // 0..63
    const int ac  = (tid & 3) << 3;      // halves 0,8,16,24
    const int br  = tid >> 4;            // 0..15 (+t*16)
    const int bc  = (tid & 15) << 3;     // halves 0..120

    const __nv_bfloat16* AgH = g_Whi + (size_t)(m0g + ar) * 256 + ac;
    const __nv_bfloat16* AgL = g_Wlo + (size_t)(m0g + ar) * 256 + ac;
    const __nv_bfloat16* BgH = g_Xhi + ((size_t)(b * 256 + br)) * 1024 + n0 + bc;
    const __nv_bfloat16* BgL = g_Xlo + ((size_t)(b * 256 + br)) * 1024 + n0 + bc;

    const uint32_t adst = (uint32_t)(ar * SKA + ac) * 2u;
    const uint32_t bdst = (uint32_t)(br * SKB + bc) * 2u;

    // issue loads for chunk ch into stage buffer
    auto issue = [&](int ch) {
        const uint32_t stb = sm_base + (ch % 3) * STG_BYTES;
        const int k0 = ch * 32;
        CP_ASYNC16(stb + adst,          AgH + k0);
        CP_ASYNC16(stb + OFF_AL + adst, AgL + k0);
        #pragma unroll
        for (int t = 0; t < 2; t++) {
            uint32_t d = bdst + (uint32_t)(t * 16 * SKB) * 2u;
            CP_ASYNC16(stb + OFF_BH + d, BgH + (size_t)(k0 + t * 16) * 1024);
            CP_ASYNC16(stb + OFF_BL + d, BgL + (size_t)(k0 + t * 16) * 1024);
        }
        CP_COMMIT();
    };

    issue(0);
    issue(1);

    float acc[2][4][4];
    #pragma unroll
    for (int i = 0; i < 2; i++)
        #pragma unroll
        for (int j = 0; j < 4; j++)
            #pragma unroll
            for (int r = 0; r < 4; r++) acc[i][j][r] = 0.f;

    #pragma unroll
    for (int ch = 0; ch < 8; ch++) {
        if (ch + 2 < 8) issue(ch + 2);
        if (ch <= 5) { CP_WAIT(2); }
        else if (ch == 6) { CP_WAIT(1); }
        else { CP_WAIT(0); }
        __syncthreads();

        const uint32_t stb = sm_base + (ch % 3) * STG_BYTES;
        #pragma unroll
        for (int ks = 0; ks < 2; ks++) {
            const int kk = ks * 16;
            uint32_t afh[2][4], afl[2][4];
            #pragma unroll
            for (int mt = 0; mt < 2; mt++) {
                uint32_t aoff = (uint32_t)((wm * 32 + mt * 16 + (lane & 15)) * SKA
                                           + kk + ((lane >> 4) << 3)) * 2u;
                ldsm_x4(afh[mt], stb + aoff);
                ldsm_x4(afl[mt], stb + OFF_AL + aoff);
            }
            uint32_t bfh[4][2], bfl[4][2];
            #pragma unroll
            for (int p = 0; p < 2; p++) {
                uint32_t boff = (uint32_t)((kk + (lane & 15)) * SKB
                                           + wn * 32 + p * 16 + ((lane >> 4) << 3)) * 2u;
                uint32_t r[4];
                ldsm_x4_t(r, stb + OFF_BH + boff);
                bfh[p * 2][0] = r[0]; bfh[p * 2][1] = r[1];
                bfh[p * 2 + 1][0] = r[2]; bfh[p * 2 + 1][1] = r[3];
                ldsm_x4_t(r, stb + OFF_BL + boff);
                bfl[p * 2][0] = r[0]; bfl[p * 2][1] = r[1];
                bfl[p * 2 + 1][0] = r[2]; bfl[p * 2 + 1][1] = r[3];
            }
            #pragma unroll
            for (int mt = 0; mt < 2; mt++)
                #pragma unroll
                for (int nt = 0; nt < 4; nt++) {
                    mma_bf16(acc[mt][nt], afh[mt], bfh[nt][0], bfh[nt][1]);
                    mma_bf16(acc[mt][nt], afh[mt], bfl[nt][0], bfl[nt][1]);
                    mma_bf16(acc[mt][nt], afl[mt], bfh[nt][0], bfh[nt][1]);
                }
        }
        __syncthreads();
    }

    // ---- epilogue
    const int mat = m0g >> 8;
    float* outp = (mat == 0) ? g_q : (mat == 1) ? g_k : g_v;
    const int orow = (m0g & 255) + wm * 32;
    #pragma unroll
    for (int mt = 0; mt < 2; mt++) {
        int o = orow + mt * 16 + (lane >> 2);
        #pragma unroll
        for (int nt = 0; nt < 4; nt++) {
            int n = n0 + wn * 32 + nt * 8 + ((lane & 3) << 1);
            float* og = outp + ((size_t)(b * CC + o)) * HWN + n;
            *(float2*)og = make_float2(acc[mt][nt][0], acc[mt][nt][1]);
            *(float2*)(og + 8 * HWN) = make_float2(acc[mt][nt][2], acc[mt][nt][3]);
        }
    }
}

// ---------------------------------------------------------------------------
// Windowed softmax attention: 512 blocks x 2 channels each (all resident).
// ---------------------------------------------------------------------------
__device__ __forceinline__ float ex2f(float x) {
    float y;
    asm("ex2.approx.ftz.f32 %0, %1;" : "=f"(y) : "f"(x));
    return y;
}

__global__ __launch_bounds__(256) void attn_kernel(
    const float* __restrict__ rel_h,
    const float* __restrict__ rel_w,
    float* __restrict__ out)
{
    __shared__ float ks[PHW];
    __shared__ float vs[PHW];
    __shared__ float brow_s[8];

    const int tid = threadIdx.x;

    // zero padded borders once (interior fully overwritten each rep)
    for (int i = tid; i < PHW; i += 256) { ks[i] = 0.f; vs[i] = 0.f; }

    for (int rep = 0; rep < 2; rep++) {
        const int j = blockIdx.x * 2 + rep;     // 0..1023
        const int b = j >> 8;
        const int c = j & 255;
        const bool hsel = (c < CC / 2);

        __syncthreads();   // previous rep's readers done before overwrite
        if (tid < KW)
            brow_s[tid] = hsel ? rel_h[c * KW + tid] : rel_w[(c - CC / 2) * KW + tid];
        const float* kg = g_k + ((size_t)(b * CC + c)) * HWN;
        const float* vg = g_v + ((size_t)(b * CC + c)) * HWN;
        for (int p = tid; p < HWN; p += 256) {
            int h = p >> 5, w = p & 31;
            int pi = (h + 3) * PW + (w + 3);
            ks[pi] = kg[p];
            vs[pi] = vg[p];
        }
        __syncthreads();

        const float* qg = g_q + ((size_t)(b * CC + c)) * HWN;
        float*       og = out + ((size_t)(b * CC + c)) * HWN;

        const int p0 = tid * 4;
        const int h  = p0 >> 5;
        const int w0 = p0 & 31;
        const float LOG2E = 1.4426950408889634f;

        float4 qv = *(const float4*)(qg + p0);
        float q2[4] = { qv.x * LOG2E, qv.y * LOG2E, qv.z * LOG2E, qv.w * LOG2E };
        float qb[4][KW];
        #pragma unroll
        for (int jj = 0; jj < 4; jj++)
            #pragma unroll
            for (int i = 0; i < KW; i++)
                qb[jj][i] = q2[jj] * brow_s[i];

        float acc[4] = {0.f, 0.f, 0.f, 0.f};
        float sum[4] = {0.f, 0.f, 0.f, 0.f};

        if (hsel) {
            #pragma unroll
            for (int u = 0; u < KW; u++) {
                const int rbase = (h + u) * PW + w0;
                float kr[10], vr[10];
                #pragma unroll
                for (int i = 0; i < 10; i++) { kr[i] = ks[rbase + i]; vr[i] = vs[rbase + i]; }
                #pragma unroll
                for (int v = 0; v < KW; v++) {
                    #pragma unroll
                    for (int jj = 0; jj < 4; jj++) {
                        float t = fmaf(q2[jj], kr[v + jj], qb[jj][u]);
                        float e = ex2f(t);
                        sum[jj] += e;
                        acc[jj]  = fmaf(e, vr[v + jj], acc[jj]);
                    }
                }
            }
        } else {
            #pragma unroll
            for (int u = 0; u < KW; u++) {
                const int rbase = (h + u) * PW + w0;
                float kr[10], vr[10];
                #pragma unroll
                for (int i = 0; i < 10; i++) { kr[i] = ks[rbase + i]; vr[i] = vs[rbase + i]; }
                #pragma unroll
                for (int v = 0; v < KW; v++) {
                    #pragma unroll
                    for (int jj = 0; jj < 4; jj++) {
                        float t = fmaf(q2[jj], kr[v + jj], qb[jj][v]);
                        float e = ex2f(t);
                        sum[jj] += e;
                        acc[jj]  = fmaf(e, vr[v + jj], acc[jj]);
                    }
                }
            }
        }

        float4 r;
        r.x = __fdividef(acc[0], sum[0]);
        r.y = __fdividef(acc[1], sum[1]);
        r.z = __fdividef(acc[2], sum[2]);
        r.w = __fdividef(acc[3], sum[3]);
        *(float4*)(og + p0) = r;
    }
}

// ---------------------------------------------------------------------------
extern "C" void kernel_launch(void* const* d_in, const int* in_sizes, int n_in,
                              void* d_out, int out_size)
{
    const float* x     = (const float*)d_in[0];
    const float* wq    = (const float*)d_in[1];
    const float* wk    = (const float*)d_in[2];
    const float* wv    = (const float*)d_in[3];
    const float* rel_h = (const float*)d_in[4];
    const float* rel_w = (const float*)d_in[5];
    float* out = (float*)d_out;

    cudaFuncSetAttribute(qkv_mma_kernel, cudaFuncAttributeMaxDynamicSharedMemorySize,
                         SMEM_TOTAL);

    convert_kernel<<<1216, 256>>>(x, wq, wk, wv);

    dim3 gg(96, BB);
    qkv_mma_kernel<<<gg, 256, SMEM_TOTAL>>>();

    attn_kernel<<<512, 256>>>(rel_h, rel_w, out);
}

// round 6
// speedup vs baseline: 2.1183x; 1.0551x over previous
#include <cuda_runtime.h>
#include <cuda_bf16.h>
#include <cstdint>

// Problem constants
#define KW 7
#define CC 256
#define BB 4
#define HWN 1024          // 32*32
#define PW 38
#define PHW 1444          // 38*38

// Scratch (device globals)
__device__ float g_q[BB * CC * HWN];
__device__ float g_k[BB * CC * HWN];
__device__ float g_v[BB * CC * HWN];
__device__ __nv_bfloat16 g_Whi[3 * 256 * 256];
__device__ __nv_bfloat16 g_Wlo[3 * 256 * 256];
__device__ __nv_bfloat16 g_Xhi[BB * 256 * 1024];
__device__ __nv_bfloat16 g_Xlo[BB * 256 * 1024];

// ---------------------------------------------------------------------------
// helpers
// ---------------------------------------------------------------------------
__device__ __forceinline__ uint32_t smem_u32(const void* p) {
    uint32_t a;
    asm("{ .reg .u64 t; cvta.to.shared.u64 t, %1; cvt.u32.u64 %0, t; }" : "=r"(a) : "l"(p));
    return a;
}
__device__ __forceinline__ void ldsm_x4(uint32_t r[4], uint32_t addr) {
    asm volatile("ldmatrix.sync.aligned.m8n8.x4.shared.b16 {%0,%1,%2,%3}, [%4];"
                 : "=r"(r[0]), "=r"(r[1]), "=r"(r[2]), "=r"(r[3]) : "r"(addr));
}
__device__ __forceinline__ void ldsm_x4_t(uint32_t r[4], uint32_t addr) {
    asm volatile("ldmatrix.sync.aligned.m8n8.x4.trans.shared.b16 {%0,%1,%2,%3}, [%4];"
                 : "=r"(r[0]), "=r"(r[1]), "=r"(r[2]), "=r"(r[3]) : "r"(addr));
}
__device__ __forceinline__ void mma_bf16(float c[4], const uint32_t a[4],
                                         uint32_t b0, uint32_t b1) {
    asm volatile(
        "mma.sync.aligned.m16n8k16.row.col.f32.bf16.bf16.f32 "
        "{%0,%1,%2,%3}, {%4,%5,%6,%7}, {%8,%9}, {%0,%1,%2,%3};"
        : "+f"(c[0]), "+f"(c[1]), "+f"(c[2]), "+f"(c[3])
        : "r"(a[0]), "r"(a[1]), "r"(a[2]), "r"(a[3]), "r"(b0), "r"(b1));
}
__device__ __forceinline__ void split_bf(float a, __nv_bfloat16& h, __nv_bfloat16& l) {
    h = __float2bfloat16(a);
    l = __float2bfloat16(a - __bfloat162float(h));
}
__device__ __forceinline__ uint32_t pack2(__nv_bfloat16 a, __nv_bfloat16 b) {
    __nv_bfloat162 t; t.x = a; t.y = b;
    return *(uint32_t*)&t;
}
#define CP_ASYNC16(dst, src) \
    asm volatile("cp.async.cg.shared.global [%0], [%1], 16;" :: "r"(dst), "l"(src))
#define CP_COMMIT() asm volatile("cp.async.commit_group;" ::: "memory")
#define CP_WAIT(N)  asm volatile("cp.async.wait_group %0;" :: "n"(N) : "memory")

// ---------------------------------------------------------------------------
// Pre-convert with MLP=4: grid 304 x 256 threads, 4 float4 per thread.
// blocks [0,256): X;  blocks [256,304): W.
// ---------------------------------------------------------------------------
__global__ __launch_bounds__(256) void convert_kernel(
    const float* __restrict__ x,
    const float* __restrict__ wq,
    const float* __restrict__ wk,
    const float* __restrict__ wv)
{
    const int tid = threadIdx.x;
    float4 v[4];
    int i4[4];
    if (blockIdx.x < 256) {
        #pragma unroll
        for (int t = 0; t < 4; t++) {
            i4[t] = blockIdx.x * 1024 + t * 256 + tid;
            v[t] = ((const float4*)x)[i4[t]];
        }
        #pragma unroll
        for (int t = 0; t < 4; t++) {
            __nv_bfloat16 h0, l0, h1, l1, h2, l2, h3, l3;
            split_bf(v[t].x, h0, l0); split_bf(v[t].y, h1, l1);
            split_bf(v[t].z, h2, l2); split_bf(v[t].w, h3, l3);
            int base = i4[t] * 4;
            *(uint2*)&g_Xhi[base] = make_uint2(pack2(h0, h1), pack2(h2, h3));
            *(uint2*)&g_Xlo[base] = make_uint2(pack2(l0, l1), pack2(l2, l3));
        }
    } else {
        #pragma unroll
        for (int t = 0; t < 4; t++) {
            i4[t] = (blockIdx.x - 256) * 1024 + t * 256 + tid;   // 0..49151
            int mat = i4[t] >> 14;
            int off4 = i4[t] & 16383;
            const float* Wp = (mat == 0) ? wq : (mat == 1) ? wk : wv;
            v[t] = ((const float4*)Wp)[off4];
        }
        #pragma unroll
        for (int t = 0; t < 4; t++) {
            __nv_bfloat16 h0, l0, h1, l1, h2, l2, h3, l3;
            split_bf(v[t].x, h0, l0); split_bf(v[t].y, h1, l1);
            split_bf(v[t].z, h2, l2); split_bf(v[t].w, h3, l3);
            int base = i4[t] * 4;
            *(uint2*)&g_Whi[base] = make_uint2(pack2(h0, h1), pack2(h2, h3));
            *(uint2*)&g_Wlo[base] = make_uint2(pack2(l0, l1), pack2(l2, l3));
        }
    }
}

// ---------------------------------------------------------------------------
// bf16 split-precision QKV GEMM, cp.async 2-stage pipeline (3 CTAs/SM).
// 64x128 tile, BK=32, 8 warps (warptile 32x32).
// grid: x = 96 (12 m-tiles over combined 768 rows x 8 n-tiles), y = batch(4)
// ---------------------------------------------------------------------------
#define SKA 48       // A smem stride (halves)
#define SKB 136      // B smem stride (halves)
#define OFF_AL 6144
#define OFF_BH 12288
#define OFF_BL 20992
#define STG_BYTES 29696
#define SMEM_TOTAL (2 * STG_BYTES)

__global__ __launch_bounds__(256, 3) void qkv_mma_kernel()
{
    extern __shared__ char sm[];
    const uint32_t sm_base = smem_u32(sm);

    const int tid  = threadIdx.x;
    const int wid  = tid >> 5;
    const int lane = tid & 31;
    const int wm   = wid >> 2;          // 0..1 (32 rows)
    const int wn   = wid & 3;           // 0..3 (32 cols)
    const int b    = blockIdx.y;
    const int m0g  = (blockIdx.x >> 3) * 64;   // 0..704 combined row
    const int n0   = (blockIdx.x & 7) * 128;

    // per-thread cp.async coordinates
    const int ar  = tid >> 2;            // 0..63
    const int ac  = (tid & 3) << 3;      // halves 0,8,16,24
    const int br  = tid >> 4;            // 0..15 (+t*16)
    const int bc  = (tid & 15) << 3;     // halves 0..120

    const __nv_bfloat16* AgH = g_Whi + (size_t)(m0g + ar) * 256 + ac;
    const __nv_bfloat16* AgL = g_Wlo + (size_t)(m0g + ar) * 256 + ac;
    const __nv_bfloat16* BgH = g_Xhi + ((size_t)(b * 256 + br)) * 1024 + n0 + bc;
    const __nv_bfloat16* BgL = g_Xlo + ((size_t)(b * 256 + br)) * 1024 + n0 + bc;

    const uint32_t adst = (uint32_t)(ar * SKA + ac) * 2u;
    const uint32_t bdst = (uint32_t)(br * SKB + bc) * 2u;

    auto issue = [&](int ch) {
        const uint32_t stb = sm_base + (ch & 1) * STG_BYTES;
        const int k0 = ch * 32;
        CP_ASYNC16(stb + adst,          AgH + k0);
        CP_ASYNC16(stb + OFF_AL + adst, AgL + k0);
        #pragma unroll
        for (int t = 0; t < 2; t++) {
            uint32_t d = bdst + (uint32_t)(t * 16 * SKB) * 2u;
            CP_ASYNC16(stb + OFF_BH + d, BgH + (size_t)(k0 + t * 16) * 1024);
            CP_ASYNC16(stb + OFF_BL + d, BgL + (size_t)(k0 + t * 16) * 1024);
        }
        CP_COMMIT();
    };

    issue(0);
    issue(1);

    float acc[2][4][4];
    #pragma unroll
    for (int i = 0; i < 2; i++)
        #pragma unroll
        for (int j = 0; j < 4; j++)
            #pragma unroll
            for (int r = 0; r < 4; r++) acc[i][j][r] = 0.f;

    #pragma unroll
    for (int ch = 0; ch < 8; ch++) {
        if (ch < 7) { CP_WAIT(1); } else { CP_WAIT(0); }
        __syncthreads();

        const uint32_t stb = sm_base + (ch & 1) * STG_BYTES;
        #pragma unroll
        for (int ks = 0; ks < 2; ks++) {
            const int kk = ks * 16;
            uint32_t afh[2][4], afl[2][4];
            #pragma unroll
            for (int mt = 0; mt < 2; mt++) {
                uint32_t aoff = (uint32_t)((wm * 32 + mt * 16 + (lane & 15)) * SKA
                                           + kk + ((lane >> 4) << 3)) * 2u;
                ldsm_x4(afh[mt], stb + aoff);
                ldsm_x4(afl[mt], stb + OFF_AL + aoff);
            }
            uint32_t bfh[4][2], bfl[4][2];
            #pragma unroll
            for (int p = 0; p < 2; p++) {
                uint32_t boff = (uint32_t)((kk + (lane & 15)) * SKB
                                           + wn * 32 + p * 16 + ((lane >> 4) << 3)) * 2u;
                uint32_t r[4];
                ldsm_x4_t(r, stb + OFF_BH + boff);
                bfh[p * 2][0] = r[0]; bfh[p * 2][1] = r[1];
                bfh[p * 2 + 1][0] = r[2]; bfh[p * 2 + 1][1] = r[3];
                ldsm_x4_t(r, stb + OFF_BL + boff);
                bfl[p * 2][0] = r[0]; bfl[p * 2][1] = r[1];
                bfl[p * 2 + 1][0] = r[2]; bfl[p * 2 + 1][1] = r[3];
            }
            #pragma unroll
            for (int mt = 0; mt < 2; mt++)
                #pragma unroll
                for (int nt = 0; nt < 4; nt++) {
                    mma_bf16(acc[mt][nt], afh[mt], bfh[nt][0], bfh[nt][1]);
                    mma_bf16(acc[mt][nt], afh[mt], bfl[nt][0], bfl[nt][1]);
                    mma_bf16(acc[mt][nt], afl[mt], bfh[nt][0], bfh[nt][1]);
                }
        }
        __syncthreads();
        if (ch + 2 < 8) issue(ch + 2);
    }

    // ---- epilogue
    const int mat = m0g >> 8;
    float* outp = (mat == 0) ? g_q : (mat == 1) ? g_k : g_v;
    const int orow = (m0g & 255) + wm * 32;
    #pragma unroll
    for (int mt = 0; mt < 2; mt++) {
        int o = orow + mt * 16 + (lane >> 2);
        #pragma unroll
        for (int nt = 0; nt < 4; nt++) {
            int n = n0 + wn * 32 + nt * 8 + ((lane & 3) << 1);
            float* og = outp + ((size_t)(b * CC + o)) * HWN + n;
            *(float2*)og = make_float2(acc[mt][nt][0], acc[mt][nt][1]);
            *(float2*)(og + 8 * HWN) = make_float2(acc[mt][nt][2], acc[mt][nt][3]);
        }
    }
}

// ---------------------------------------------------------------------------
// Windowed softmax attention: 512 blocks x 2 channels; float4 k/v loads.
// ---------------------------------------------------------------------------
__device__ __forceinline__ float ex2f(float x) {
    float y;
    asm("ex2.approx.ftz.f32 %0, %1;" : "=f"(y) : "f"(x));
    return y;
}

__global__ __launch_bounds__(256) void attn_kernel(
    const float* __restrict__ rel_h,
    const float* __restrict__ rel_w,
    float* __restrict__ out)
{
    __shared__ float ks[PHW];
    __shared__ float vs[PHW];
    __shared__ float brow_s[8];

    const int tid = threadIdx.x;
    const int p0 = tid * 4;
    const int h  = p0 >> 5;
    const int w0 = p0 & 31;
    const int pi0 = (h + 3) * PW + (w0 + 3);

    // zero padded borders once (interior fully overwritten each rep)
    for (int i = tid; i < PHW; i += 256) { ks[i] = 0.f; vs[i] = 0.f; }

    for (int rep = 0; rep < 2; rep++) {
        const int j = blockIdx.x * 2 + rep;     // 0..1023
        const int b = j >> 8;
        const int c = j & 255;
        const bool hsel = (c < CC / 2);

        __syncthreads();   // previous rep's readers done before overwrite
        if (tid < KW)
            brow_s[tid] = hsel ? rel_h[c * KW + tid] : rel_w[(c - CC / 2) * KW + tid];
        const float* kg = g_k + ((size_t)(b * CC + c)) * HWN;
        const float* vg = g_v + ((size_t)(b * CC + c)) * HWN;
        {
            float4 k4 = ((const float4*)kg)[tid];
            float4 v4 = ((const float4*)vg)[tid];
            ks[pi0 + 0] = k4.x; ks[pi0 + 1] = k4.y; ks[pi0 + 2] = k4.z; ks[pi0 + 3] = k4.w;
            vs[pi0 + 0] = v4.x; vs[pi0 + 1] = v4.y; vs[pi0 + 2] = v4.z; vs[pi0 + 3] = v4.w;
        }
        __syncthreads();

        const float* qg = g_q + ((size_t)(b * CC + c)) * HWN;
        float*       og = out + ((size_t)(b * CC + c)) * HWN;

        const float LOG2E = 1.4426950408889634f;
        float4 qv = *(const float4*)(qg + p0);
        float q2[4] = { qv.x * LOG2E, qv.y * LOG2E, qv.z * LOG2E, qv.w * LOG2E };
        float qb[4][KW];
        #pragma unroll
        for (int jj = 0; jj < 4; jj++)
            #pragma unroll
            for (int i = 0; i < KW; i++)
                qb[jj][i] = q2[jj] * brow_s[i];

        float acc[4] = {0.f, 0.f, 0.f, 0.f};
        float sum[4] = {0.f, 0.f, 0.f, 0.f};

        if (hsel) {
            #pragma unroll
            for (int u = 0; u < KW; u++) {
                const int rbase = (h + u) * PW + w0;
                float kr[10], vr[10];
                #pragma unroll
                for (int i = 0; i < 10; i++) { kr[i] = ks[rbase + i]; vr[i] = vs[rbase + i]; }
                #pragma unroll
                for (int v = 0; v < KW; v++) {
                    #pragma unroll
                    for (int jj = 0; jj < 4; jj++) {
                        float t = fmaf(q2[jj], kr[v + jj], qb[jj][u]);
                        float e = ex2f(t);
                        sum[jj] += e;
                        acc[jj]  = fmaf(e, vr[v + jj], acc[jj]);
                    }
                }
            }
        } else {
            #pragma unroll
            for (int u = 0; u < KW; u++) {
                const int rbase = (h + u) * PW + w0;
                float kr[10], vr[10];
                #pragma unroll
                for (int i = 0; i < 10; i++) { kr[i] = ks[rbase + i]; vr[i] = vs[rbase + i]; }
                #pragma unroll
                for (int v = 0; v < KW; v++) {
                    #pragma unroll
                    for (int jj = 0; jj < 4; jj++) {
                        float t = fmaf(q2[jj], kr[v + jj], qb[jj][v]);
                        float e = ex2f(t);
                        sum[jj] += e;
                        acc[jj]  = fmaf(e, vr[v + jj], acc[jj]);
                    }
                }
            }
        }

        float4 r;
        r.x = __fdividef(acc[0], sum[0]);
        r.y = __fdividef(acc[1], sum[1]);
        r.z = __fdividef(acc[2], sum[2]);
        r.w = __fdividef(acc[3], sum[3]);
        *(float4*)(og + p0) = r;
    }
}

// ---------------------------------------------------------------------------
extern "C" void kernel_launch(void* const* d_in, const int* in_sizes, int n_in,
                              void* d_out, int out_size)
{
    const float* x     = (const float*)d_in[0];
    const float* wq    = (const float*)d_in[1];
    const float* wk    = (const float*)d_in[2];
    const float* wv    = (const float*)d_in[3];
    const float* rel_h = (const float*)d_in[4];
    const float* rel_w = (const float*)d_in[5];
    float* out = (float*)d_out;

    cudaFuncSetAttribute(qkv_mma_kernel, cudaFuncAttributeMaxDynamicSharedMemorySize,
                         SMEM_TOTAL);

    convert_kernel<<<304, 256>>>(x, wq, wk, wv);

    dim3 gg(96, BB);
    qkv_mma_kernel<<<gg, 256, SMEM_TOTAL>>>();

    attn_kernel<<<512, 256>>>(rel_h, rel_w, out);
}

// round 7
// speedup vs baseline: 2.2225x; 1.0492x over previous
#include <cuda_runtime.h>
#include <cuda_bf16.h>
#include <cstdint>

// Problem constants
#define KW 7
#define CC 256
#define BB 4
#define HWN 1024          // 32*32
#define PW2 40            // padded smem row stride (floats), 160B = 16B-aligned rows
#define PHW2 (38 * PW2)   // 1520 floats per plane

// Scratch (device globals)
__device__ float g_q[BB * CC * HWN];
__device__ float g_k[BB * CC * HWN];
__device__ float g_v[BB * CC * HWN];
__device__ __nv_bfloat16 g_Whi[3 * 256 * 256];
__device__ __nv_bfloat16 g_Wlo[3 * 256 * 256];
__device__ __nv_bfloat16 g_Xhi[BB * 256 * 1024];
__device__ __nv_bfloat16 g_Xlo[BB * 256 * 1024];

// ---------------------------------------------------------------------------
// helpers
// ---------------------------------------------------------------------------
__device__ __forceinline__ uint32_t smem_u32(const void* p) {
    uint32_t a;
    asm("{ .reg .u64 t; cvta.to.shared.u64 t, %1; cvt.u32.u64 %0, t; }" : "=r"(a) : "l"(p));
    return a;
}
__device__ __forceinline__ void ldsm_x4(uint32_t r[4], uint32_t addr) {
    asm volatile("ldmatrix.sync.aligned.m8n8.x4.shared.b16 {%0,%1,%2,%3}, [%4];"
                 : "=r"(r[0]), "=r"(r[1]), "=r"(r[2]), "=r"(r[3]) : "r"(addr));
}
__device__ __forceinline__ void ldsm_x4_t(uint32_t r[4], uint32_t addr) {
    asm volatile("ldmatrix.sync.aligned.m8n8.x4.trans.shared.b16 {%0,%1,%2,%3}, [%4];"
                 : "=r"(r[0]), "=r"(r[1]), "=r"(r[2]), "=r"(r[3]) : "r"(addr));
}
__device__ __forceinline__ void mma_bf16(float c[4], const uint32_t a[4],
                                         uint32_t b0, uint32_t b1) {
    asm volatile(
        "mma.sync.aligned.m16n8k16.row.col.f32.bf16.bf16.f32 "
        "{%0,%1,%2,%3}, {%4,%5,%6,%7}, {%8,%9}, {%0,%1,%2,%3};"
        : "+f"(c[0]), "+f"(c[1]), "+f"(c[2]), "+f"(c[3])
        : "r"(a[0]), "r"(a[1]), "r"(a[2]), "r"(a[3]), "r"(b0), "r"(b1));
}
__device__ __forceinline__ void split_bf(float a, __nv_bfloat16& h, __nv_bfloat16& l) {
    h = __float2bfloat16(a);
    l = __float2bfloat16(a - __bfloat162float(h));
}
__device__ __forceinline__ uint32_t pack2(__nv_bfloat16 a, __nv_bfloat16 b) {
    __nv_bfloat162 t; t.x = a; t.y = b;
    return *(uint32_t*)&t;
}
#define CP_ASYNC16(dst, src) \
    asm volatile("cp.async.cg.shared.global [%0], [%1], 16;" :: "r"(dst), "l"(src))
#define CP_COMMIT() asm volatile("cp.async.commit_group;" ::: "memory")
#define CP_WAIT(N)  asm volatile("cp.async.wait_group %0;" :: "n"(N) : "memory")

// ---------------------------------------------------------------------------
// Pre-convert (proven config): grid 1216 x 256, 1 float4/thread.
// blocks [0,1024): X;  blocks [1024,1216): W.
// ---------------------------------------------------------------------------
__global__ __launch_bounds__(256) void convert_kernel(
    const float* __restrict__ x,
    const float* __restrict__ wq,
    const float* __restrict__ wk,
    const float* __restrict__ wv)
{
    const int tid = threadIdx.x;
    __nv_bfloat16 h0, l0, h1, l1, h2, l2, h3, l3;
    if (blockIdx.x < 1024) {
        int i4 = blockIdx.x * 256 + tid;
        float4 v = ((const float4*)x)[i4];
        split_bf(v.x, h0, l0); split_bf(v.y, h1, l1);
        split_bf(v.z, h2, l2); split_bf(v.w, h3, l3);
        int base = i4 * 4;
        *(uint2*)&g_Xhi[base] = make_uint2(pack2(h0, h1), pack2(h2, h3));
        *(uint2*)&g_Xlo[base] = make_uint2(pack2(l0, l1), pack2(l2, l3));
    } else {
        int i4 = (blockIdx.x - 1024) * 256 + tid;
        int mat = i4 >> 14;
        int off4 = i4 & 16383;
        const float* Wp = (mat == 0) ? wq : (mat == 1) ? wk : wv;
        float4 v = ((const float4*)Wp)[off4];
        split_bf(v.x, h0, l0); split_bf(v.y, h1, l1);
        split_bf(v.z, h2, l2); split_bf(v.w, h3, l3);
        int base = i4 * 4;
        *(uint2*)&g_Whi[base] = make_uint2(pack2(h0, h1), pack2(h2, h3));
        *(uint2*)&g_Wlo[base] = make_uint2(pack2(l0, l1), pack2(l2, l3));
    }
}

// ---------------------------------------------------------------------------
// bf16 split-precision QKV GEMM, cp.async 2-stage pipeline (3 CTAs/SM).
// 64x128 tile, BK=32, 8 warps (warptile 32x32).
// grid: x = 96 (12 m-tiles over combined 768 rows x 8 n-tiles), y = batch(4)
// ---------------------------------------------------------------------------
#define SKA 48       // A smem stride (halves)
#define SKB 136      // B smem stride (halves)
#define OFF_AL 6144
#define OFF_BH 12288
#define OFF_BL 20992
#define STG_BYTES 29696
#define SMEM_TOTAL (2 * STG_BYTES)

__global__ __launch_bounds__(256, 3) void qkv_mma_kernel()
{
    extern __shared__ char sm[];
    const uint32_t sm_base = smem_u32(sm);

    const int tid  = threadIdx.x;
    const int wid  = tid >> 5;
    const int lane = tid & 31;
    const int wm   = wid >> 2;
    const int wn   = wid & 3;
    const int b    = blockIdx.y;
    const int m0g  = (blockIdx.x >> 3) * 64;
    const int n0   = (blockIdx.x & 7) * 128;

    const int ar  = tid >> 2;
    const int ac  = (tid & 3) << 3;
    const int br  = tid >> 4;
    const int bc  = (tid & 15) << 3;

    const __nv_bfloat16* AgH = g_Whi + (size_t)(m0g + ar) * 256 + ac;
    const __nv_bfloat16* AgL = g_Wlo + (size_t)(m0g + ar) * 256 + ac;
    const __nv_bfloat16* BgH = g_Xhi + ((size_t)(b * 256 + br)) * 1024 + n0 + bc;
    const __nv_bfloat16* BgL = g_Xlo + ((size_t)(b * 256 + br)) * 1024 + n0 + bc;

    const uint32_t adst = (uint32_t)(ar * SKA + ac) * 2u;
    const uint32_t bdst = (uint32_t)(br * SKB + bc) * 2u;

    auto issue = [&](int ch) {
        const uint32_t stb = sm_base + (ch & 1) * STG_BYTES;
        const int k0 = ch * 32;
        CP_ASYNC16(stb + adst,          AgH + k0);
        CP_ASYNC16(stb + OFF_AL + adst, AgL + k0);
        #pragma unroll
        for (int t = 0; t < 2; t++) {
            uint32_t d = bdst + (uint32_t)(t * 16 * SKB) * 2u;
            CP_ASYNC16(stb + OFF_BH + d, BgH + (size_t)(k0 + t * 16) * 1024);
            CP_ASYNC16(stb + OFF_BL + d, BgL + (size_t)(k0 + t * 16) * 1024);
        }
        CP_COMMIT();
    };

    issue(0);
    issue(1);

    float acc[2][4][4];
    #pragma unroll
    for (int i = 0; i < 2; i++)
        #pragma unroll
        for (int j = 0; j < 4; j++)
            #pragma unroll
            for (int r = 0; r < 4; r++) acc[i][j][r] = 0.f;

    #pragma unroll
    for (int ch = 0; ch < 8; ch++) {
        if (ch < 7) { CP_WAIT(1); } else { CP_WAIT(0); }
        __syncthreads();

        const uint32_t stb = sm_base + (ch & 1) * STG_BYTES;
        #pragma unroll
        for (int ks = 0; ks < 2; ks++) {
            const int kk = ks * 16;
            uint32_t afh[2][4], afl[2][4];
            #pragma unroll
            for (int mt = 0; mt < 2; mt++) {
                uint32_t aoff = (uint32_t)((wm * 32 + mt * 16 + (lane & 15)) * SKA
                                           + kk + ((lane >> 4) << 3)) * 2u;
                ldsm_x4(afh[mt], stb + aoff);
                ldsm_x4(afl[mt], stb + OFF_AL + aoff);
            }
            uint32_t bfh[4][2], bfl[4][2];
            #pragma unroll
            for (int p = 0; p < 2; p++) {
                uint32_t boff = (uint32_t)((kk + (lane & 15)) * SKB
                                           + wn * 32 + p * 16 + ((lane >> 4) << 3)) * 2u;
                uint32_t r[4];
                ldsm_x4_t(r, stb + OFF_BH + boff);
                bfh[p * 2][0] = r[0]; bfh[p * 2][1] = r[1];
                bfh[p * 2 + 1][0] = r[2]; bfh[p * 2 + 1][1] = r[3];
                ldsm_x4_t(r, stb + OFF_BL + boff);
                bfl[p * 2][0] = r[0]; bfl[p * 2][1] = r[1];
                bfl[p * 2 + 1][0] = r[2]; bfl[p * 2 + 1][1] = r[3];
            }
            #pragma unroll
            for (int mt = 0; mt < 2; mt++)
                #pragma unroll
                for (int nt = 0; nt < 4; nt++) {
                    mma_bf16(acc[mt][nt], afh[mt], bfh[nt][0], bfh[nt][1]);
                    mma_bf16(acc[mt][nt], afh[mt], bfl[nt][0], bfl[nt][1]);
                    mma_bf16(acc[mt][nt], afl[mt], bfh[nt][0], bfh[nt][1]);
                }
        }
        __syncthreads();
        if (ch + 2 < 8) issue(ch + 2);
    }

    // ---- epilogue
    const int mat = m0g >> 8;
    float* outp = (mat == 0) ? g_q : (mat == 1) ? g_k : g_v;
    const int orow = (m0g & 255) + wm * 32;
    #pragma unroll
    for (int mt = 0; mt < 2; mt++) {
        int o = orow + mt * 16 + (lane >> 2);
        #pragma unroll
        for (int nt = 0; nt < 4; nt++) {
            int n = n0 + wn * 32 + nt * 8 + ((lane & 3) << 1);
            float* og = outp + ((size_t)(b * CC + o)) * HWN + n;
            *(float2*)og = make_float2(acc[mt][nt][0], acc[mt][nt][1]);
            *(float2*)(og + 8 * HWN) = make_float2(acc[mt][nt][2], acc[mt][nt][3]);
        }
    }
}

// ---------------------------------------------------------------------------
// Windowed softmax attention: 512 blocks x 2 channels, cp.async double-buffered.
// Padded plane: 38 rows x 40 floats, pixel (hh,ww) at [(hh+3)*40 + ww+4].
// ---------------------------------------------------------------------------
__device__ __forceinline__ float ex2f(float x) {
    float y;
    asm("ex2.approx.ftz.f32 %0, %1;" : "=f"(y) : "f"(x));
    return y;
}

__global__ __launch_bounds__(256) void attn_kernel(
    const float* __restrict__ rel_h,
    const float* __restrict__ rel_w,
    float* __restrict__ out)
{
    __shared__ float ks[2][PHW2];
    __shared__ float vs[2][PHW2];
    __shared__ float brow_s[2][8];

    const int tid = threadIdx.x;
    const int p0 = tid * 4;
    const int h  = p0 >> 5;
    const int w0 = p0 & 31;
    const int pi0 = (h + 3) * PW2 + (w0 + 4);    // 16B-aligned dst

    // zero both buffers (borders must be zero; interior overwritten by cp.async)
    for (int i = tid; i < PHW2; i += 256) {
        ks[0][i] = 0.f; ks[1][i] = 0.f;
        vs[0][i] = 0.f; vs[1][i] = 0.f;
    }

    const int j0 = blockIdx.x * 2;
    const int b0 = j0 >> 8,       c0 = j0 & 255;
    const int b1 = (j0 + 1) >> 8, c1 = (j0 + 1) & 255;
    const bool hsel0 = (c0 < CC / 2);
    const bool hsel1 = (c1 < CC / 2);

    if (tid < KW) {
        brow_s[0][tid] = hsel0 ? rel_h[c0 * KW + tid] : rel_w[(c0 - CC / 2) * KW + tid];
        brow_s[1][tid] = hsel1 ? rel_h[c1 * KW + tid] : rel_w[(c1 - CC / 2) * KW + tid];
    }

    const uint32_t ks0 = smem_u32(&ks[0][0]) + pi0 * 4;
    const uint32_t vs0 = smem_u32(&vs[0][0]) + pi0 * 4;
    const uint32_t ks1 = smem_u32(&ks[1][0]) + pi0 * 4;
    const uint32_t vs1 = smem_u32(&vs[1][0]) + pi0 * 4;

    const float* kg0 = g_k + ((size_t)(b0 * CC + c0)) * HWN + p0;
    const float* vg0 = g_v + ((size_t)(b0 * CC + c0)) * HWN + p0;
    const float* kg1 = g_k + ((size_t)(b1 * CC + c1)) * HWN + p0;
    const float* vg1 = g_v + ((size_t)(b1 * CC + c1)) * HWN + p0;

    CP_ASYNC16(ks0, kg0); CP_ASYNC16(vs0, vg0); CP_COMMIT();
    CP_ASYNC16(ks1, kg1); CP_ASYNC16(vs1, vg1); CP_COMMIT();

    // prefetch q for both reps
    float4 qv0 = *(const float4*)(g_q + ((size_t)(b0 * CC + c0)) * HWN + p0);
    float4 qv1 = *(const float4*)(g_q + ((size_t)(b1 * CC + c1)) * HWN + p0);

    const float LOG2E = 1.4426950408889634f;

    #pragma unroll
    for (int rep = 0; rep < 2; rep++) {
        if (rep == 0) { CP_WAIT(1); } else { CP_WAIT(0); }
        __syncthreads();

        const float4 qv = (rep == 0) ? qv0 : qv1;
        const bool hsel = (rep == 0) ? hsel0 : hsel1;
        const float* ksp = ks[rep];
        const float* vsp = vs[rep];

        float q2[4] = { qv.x * LOG2E, qv.y * LOG2E, qv.z * LOG2E, qv.w * LOG2E };
        float qb[4][KW];
        #pragma unroll
        for (int jj = 0; jj < 4; jj++)
            #pragma unroll
            for (int i = 0; i < KW; i++)
                qb[jj][i] = q2[jj] * brow_s[rep][i];

        float acc[4] = {0.f, 0.f, 0.f, 0.f};
        float sum[4] = {0.f, 0.f, 0.f, 0.f};

        if (hsel) {
            #pragma unroll
            for (int u = 0; u < KW; u++) {
                const int rbase = (h + u) * PW2 + w0 + 1;
                float kr[10], vr[10];
                #pragma unroll
                for (int i = 0; i < 10; i++) { kr[i] = ksp[rbase + i]; vr[i] = vsp[rbase + i]; }
                #pragma unroll
                for (int v = 0; v < KW; v++) {
                    #pragma unroll
                    for (int jj = 0; jj < 4; jj++) {
                        float t = fmaf(q2[jj], kr[v + jj], qb[jj][u]);
                        float e = ex2f(t);
                        sum[jj] += e;
                        acc[jj]  = fmaf(e, vr[v + jj], acc[jj]);
                    }
                }
            }
        } else {
            #pragma unroll
            for (int u = 0; u < KW; u++) {
                const int rbase = (h + u) * PW2 + w0 + 1;
                float kr[10], vr[10];
                #pragma unroll
                for (int i = 0; i < 10; i++) { kr[i] = ksp[rbase + i]; vr[i] = vsp[rbase + i]; }
                #pragma unroll
                for (int v = 0; v < KW; v++) {
                    #pragma unroll
                    for (int jj = 0; jj < 4; jj++) {
                        float t = fmaf(q2[jj], kr[v + jj], qb[jj][v]);
                        float e = ex2f(t);
                        sum[jj] += e;
                        acc[jj]  = fmaf(e, vr[v + jj], acc[jj]);
                    }
                }
            }
        }

        const int j = j0 + rep;
        float* og = out + ((size_t)j) * HWN + p0;
        float4 r;
        r.x = __fdividef(acc[0], sum[0]);
        r.y = __fdividef(acc[1], sum[1]);
        r.z = __fdividef(acc[2], sum[2]);
        r.w = __fdividef(acc[3], sum[3]);
        *(float4*)og = r;
    }
}

// ---------------------------------------------------------------------------
extern "C" void kernel_launch(void* const* d_in, const int* in_sizes, int n_in,
                              void* d_out, int out_size)
{
    const float* x     = (const float*)d_in[0];
    const float* wq    = (const float*)d_in[1];
    const float* wk    = (const float*)d_in[2];
    const float* wv    = (const float*)d_in[3];
    const float* rel_h = (const float*)d_in[4];
    const float* rel_w = (const float*)d_in[5];
    float* out = (float*)d_out;

    cudaFuncSetAttribute(qkv_mma_kernel, cudaFuncAttributeMaxDynamicSharedMemorySize,
                         SMEM_TOTAL);

    convert_kernel<<<1216, 256>>>(x, wq, wk, wv);

    dim3 gg(96, BB);
    qkv_mma_kernel<<<gg, 256, SMEM_TOTAL>>>();

    attn_kernel<<<512, 256>>>(rel_h, rel_w, out);
}